// round 8
// baseline (speedup 1.0000x reference)
#include <cuda_runtime.h>
#include <math.h>

#define BATCH   4
#define N_SEQ   1024
#define D_MODEL 256
#define N_HEADS 8
#define D_HEAD  32
#define ATT_SCALE 0.17677669529663687f   // 1/sqrt(32)

// Scratch (device globals: no allocation allowed in kernel_launch)
__device__ float g_Q[BATCH * N_HEADS * N_SEQ * D_HEAD];   // [b,h,n,dk]  tf32, pre-scaled
__device__ float g_K[BATCH * N_HEADS * N_SEQ * D_HEAD];   // tf32-rounded
__device__ float g_V[BATCH * N_HEADS * N_SEQ * D_HEAD];   // tf32-rounded
__device__ float g_AO[BATCH * N_SEQ * D_MODEL];           // attention out, tf32-rounded
__device__ float g_maskval[BATCH * N_SEQ];                // 0 or -inf per key

__device__ __forceinline__ unsigned f2tf32(float f) {
    unsigned u;
    asm("cvt.rna.tf32.f32 %0, %1;" : "=r"(u) : "f"(f));
    return u;
}

#define MMA_TF32(d, a, b)                                                     \
    asm volatile(                                                             \
        "mma.sync.aligned.m16n8k8.row.col.f32.tf32.tf32.f32 "                 \
        "{%0,%1,%2,%3}, {%4,%5,%6,%7}, {%8,%9}, {%0,%1,%2,%3};\n"             \
        : "+f"((d)[0]), "+f"((d)[1]), "+f"((d)[2]), "+f"((d)[3])              \
        : "r"((a)[0]), "r"((a)[1]), "r"((a)[2]), "r"((a)[3]),                 \
          "r"((b)[0]), "r"((b)[1]))

__device__ __forceinline__ void cp_async16(void* s, const void* g) {
    unsigned sa = (unsigned)__cvta_generic_to_shared(s);
    asm volatile("cp.async.cg.shared.global [%0], [%1], 16;" :: "r"(sa), "l"(g));
}
#define CP_COMMIT() asm volatile("cp.async.commit_group;")
#define CP_WAIT0()  asm volatile("cp.async.wait_group 0;")
#define CP_WAIT1()  asm volatile("cp.async.wait_group 1;")
#define CP_WAIT2()  asm volatile("cp.async.wait_group 2;")

// ---------------------------------------------------------------------------
// Mask prep (parallel): detect storage dtype (int32 / float32 / uint8),
// expand to float additive mask (0 or -inf).
// ---------------------------------------------------------------------------
__global__ void prep_mask_kernel(const void* __restrict__ mraw) {
    const int tid = threadIdx.x;   // 256
    const unsigned* mi = (const unsigned*)mraw;
    int ok_int = 1, ok_float = 1;
    for (int i = tid; i < 1024; i += 256) {
        unsigned v = mi[i];
        if (v > 1u) ok_int = 0;
        if (v != 0u && v != 0x3F800000u) ok_float = 0;
    }
    int all_int   = __syncthreads_and(ok_int);
    int all_float = __syncthreads_and(ok_float);
    const int mode = all_int ? 0 : (all_float ? 1 : 2);
    const float NEG_INF = __int_as_float(0xff800000);
    for (int i = tid; i < BATCH * N_SEQ; i += 256) {
        int masked;
        if (mode == 0)      masked = ((const int*)mraw)[i] != 0;
        else if (mode == 1) masked = ((const unsigned*)mraw)[i] != 0u;
        else                masked = ((const unsigned char*)mraw)[i] != 0;
        g_maskval[i] = masked ? NEG_INF : 0.0f;
    }
}

// ---------------------------------------------------------------------------
// Fused QKV projection, tf32 tensor cores, 2-stage cp.async pipeline.
// grid=(64,4,3), block=128. Q additionally scaled by ATT_SCALE.
// ---------------------------------------------------------------------------
__global__ __launch_bounds__(128) void gemm_qkv_tc(
    const float* __restrict__ x,
    const float* __restrict__ Wq, const float* __restrict__ Wk, const float* __restrict__ Wv,
    const float* __restrict__ bq, const float* __restrict__ bk, const float* __restrict__ bv)
{
    __shared__ float As[2][64][36];
    __shared__ float Ws[2][64][36];

    const int z = blockIdx.z;
    const float* W    = (z == 0) ? Wq : (z == 1) ? Wk : Wv;
    const float* bias = (z == 0) ? bq : (z == 1) ? bk : bv;
    float* out        = (z == 0) ? g_Q : (z == 1) ? g_K : g_V;

    const int tid  = threadIdx.x;
    const int lane = tid & 31;
    const int w    = tid >> 5;
    const int g    = lane >> 2;
    const int t    = lane & 3;
    const int w16  = w * 16;
    const int rbase = blockIdx.x * 64;
    const int cbase = blockIdx.y * 64;

    float sc[8][4];
#pragma unroll
    for (int n = 0; n < 8; n++)
#pragma unroll
        for (int j = 0; j < 4; j++) sc[n][j] = 0.0f;

    auto prefetch = [&](int c) {
        const int k0 = c * 32, st = c & 1;
#pragma unroll
        for (int it = 0; it < 4; it++) {
            int s = it * 128 + tid;
            int row = s >> 3;
            int c4 = (s & 7) * 4;
            cp_async16(&As[st][row][c4], &x[(size_t)(rbase + row) * D_MODEL + k0 + c4]);
        }
#pragma unroll
        for (int it = 0; it < 4; it++) {
            int s = it * 128 + tid;
            int row = s >> 3;
            int c4 = (s & 7) * 4;
            cp_async16(&Ws[st][row][c4], &W[(size_t)(cbase + row) * D_MODEL + k0 + c4]);
        }
        CP_COMMIT();
    };

    prefetch(0);
    for (int c = 0; c < 8; c++) {
        const int st = c & 1;
        if (c < 7) { prefetch(c + 1); CP_WAIT1(); }
        else       { CP_WAIT0(); }
        __syncthreads();

        unsigned qa[4][4];
#pragma unroll
        for (int kk = 0; kk < 4; kk++) {
            qa[kk][0] = f2tf32(As[st][w16 + g    ][kk * 8 + t    ]);
            qa[kk][1] = f2tf32(As[st][w16 + g + 8][kk * 8 + t    ]);
            qa[kk][2] = f2tf32(As[st][w16 + g    ][kk * 8 + t + 4]);
            qa[kk][3] = f2tf32(As[st][w16 + g + 8][kk * 8 + t + 4]);
        }
#pragma unroll
        for (int n8 = 0; n8 < 8; n8++) {
#pragma unroll
            for (int kk = 0; kk < 4; kk++) {
                unsigned bb[2];
                bb[0] = f2tf32(Ws[st][n8 * 8 + g][kk * 8 + t    ]);
                bb[1] = f2tf32(Ws[st][n8 * 8 + g][kk * 8 + t + 4]);
                MMA_TF32(sc[n8], qa[kk], bb);
            }
        }
        __syncthreads();
    }

    const float scale = (z == 0) ? ATT_SCALE : 1.0f;
#pragma unroll
    for (int n8 = 0; n8 < 8; n8++) {
        int c0 = cbase + n8 * 8 + 2 * t;
        float b0v = bias[c0], b1v = bias[c0 + 1];
        int r0 = rbase + w16 + g;
        int r1 = r0 + 8;
        float2 v0, v1;
        v0.x = __uint_as_float(f2tf32((sc[n8][0] + b0v) * scale));
        v0.y = __uint_as_float(f2tf32((sc[n8][1] + b1v) * scale));
        v1.x = __uint_as_float(f2tf32((sc[n8][2] + b0v) * scale));
        v1.y = __uint_as_float(f2tf32((sc[n8][3] + b1v) * scale));
        int h = c0 >> 5, dk = c0 & 31;
        int b0i = r0 >> 10, n0 = r0 & 1023;
        int b1i = r1 >> 10, n1 = r1 & 1023;
        *(float2*)&out[(size_t)(((b0i << 3) + h) * N_SEQ + n0) * D_HEAD + dk] = v0;
        *(float2*)&out[(size_t)(((b1i << 3) + h) * N_SEQ + n1) * D_HEAD + dk] = v1;
    }
}

// ---------------------------------------------------------------------------
// Output projection, tf32 tensor cores, 2-stage cp.async pipeline.
// grid=(64,4), block=128. A = g_AO (already tf32-rounded).
// ---------------------------------------------------------------------------
__global__ __launch_bounds__(128) void gemm_o_tc(
    const float* __restrict__ W, const float* __restrict__ bias,
    float* __restrict__ out)
{
    __shared__ float As[2][64][36];
    __shared__ float Ws[2][64][36];

    const int tid  = threadIdx.x;
    const int lane = tid & 31;
    const int w    = tid >> 5;
    const int g    = lane >> 2;
    const int t    = lane & 3;
    const int w16  = w * 16;
    const int rbase = blockIdx.x * 64;
    const int cbase = blockIdx.y * 64;

    float sc[8][4];
#pragma unroll
    for (int n = 0; n < 8; n++)
#pragma unroll
        for (int j = 0; j < 4; j++) sc[n][j] = 0.0f;

    auto prefetch = [&](int c) {
        const int k0 = c * 32, st = c & 1;
#pragma unroll
        for (int it = 0; it < 4; it++) {
            int s = it * 128 + tid;
            int row = s >> 3;
            int c4 = (s & 7) * 4;
            cp_async16(&As[st][row][c4], &g_AO[(size_t)(rbase + row) * D_MODEL + k0 + c4]);
        }
#pragma unroll
        for (int it = 0; it < 4; it++) {
            int s = it * 128 + tid;
            int row = s >> 3;
            int c4 = (s & 7) * 4;
            cp_async16(&Ws[st][row][c4], &W[(size_t)(cbase + row) * D_MODEL + k0 + c4]);
        }
        CP_COMMIT();
    };

    prefetch(0);
    for (int c = 0; c < 8; c++) {
        const int st = c & 1;
        if (c < 7) { prefetch(c + 1); CP_WAIT1(); }
        else       { CP_WAIT0(); }
        __syncthreads();

        unsigned qa[4][4];
#pragma unroll
        for (int kk = 0; kk < 4; kk++) {
            qa[kk][0] = __float_as_uint(As[st][w16 + g    ][kk * 8 + t    ]);
            qa[kk][1] = __float_as_uint(As[st][w16 + g + 8][kk * 8 + t    ]);
            qa[kk][2] = __float_as_uint(As[st][w16 + g    ][kk * 8 + t + 4]);
            qa[kk][3] = __float_as_uint(As[st][w16 + g + 8][kk * 8 + t + 4]);
        }
#pragma unroll
        for (int n8 = 0; n8 < 8; n8++) {
#pragma unroll
            for (int kk = 0; kk < 4; kk++) {
                unsigned bb[2];
                bb[0] = f2tf32(Ws[st][n8 * 8 + g][kk * 8 + t    ]);
                bb[1] = f2tf32(Ws[st][n8 * 8 + g][kk * 8 + t + 4]);
                MMA_TF32(sc[n8], qa[kk], bb);
            }
        }
        __syncthreads();
    }

#pragma unroll
    for (int n8 = 0; n8 < 8; n8++) {
        int c0 = cbase + n8 * 8 + 2 * t;
        float b0v = bias[c0], b1v = bias[c0 + 1];
        int r0 = rbase + w16 + g;
        int r1 = r0 + 8;
        float2 v0, v1;
        v0.x = sc[n8][0] + b0v;  v0.y = sc[n8][1] + b1v;
        v1.x = sc[n8][2] + b0v;  v1.y = sc[n8][3] + b1v;
        *(float2*)&out[(size_t)r0 * D_MODEL + c0] = v0;
        *(float2*)&out[(size_t)r1 * D_MODEL + c0] = v1;
    }
}

// ---------------------------------------------------------------------------
// PERSISTENT tensor-core flash attention. grid=148 (1 CTA/SM), block=128.
// CTA -> (batch b = cta&3, c4 = cta>>2 in [0,37)); items: local = c4 + 37*j,
// j < ni (ni=4 for c4<17 else 3; covers all 128 q-tile items per batch).
// All items of a CTA share b -> mask loaded ONCE per CTA.
// Continuous global tile stream gt = 0..ni*16: group(gt+3) issued at end of
// tile gt, crossing item boundaries with no pipeline drain. 3-deep pipe,
// slot = gt%3. Q for next item prefetched into registers at tile 13.
// Dynamic smem (floats):
//   KsB[3][64*36] @ 0      (6912)
//   VsB[3][64*40] @ 6912   (7680)
//   Ps  [64*68]   @ 14592  (4352)
//   Bias[3][3][64*64] @ 18944 (36864)  16B-chunk XOR swizzle, stride 64
//   Msk [1024]    @ 55808  (1024)
// total 56832 floats = 227328 B
// ---------------------------------------------------------------------------
#define ATTN_SMEM_BYTES (56832 * 4)

__global__ __launch_bounds__(128) void attn_tc_kernel(
    const float* __restrict__ edge,
    const float* __restrict__ spat,
    const float* __restrict__ rnk)
{
    extern __shared__ float dsm[];
    float* KsB  = dsm;
    float* VsB  = dsm + 6912;
    float* Ps   = dsm + 14592;
    float* Bias = dsm + 18944;
    float* Msk  = dsm + 55808;

    const int tid  = threadIdx.x;
    const int lane = tid & 31;
    const int w    = tid >> 5;
    const int g    = lane >> 2;
    const int t    = lane & 3;
    const int w16  = w * 16;

    const int cta = blockIdx.x;
    const int b   = cta & 3;          // batch index (fixed per CTA)
    const int c4  = cta >> 2;         // 0..36
    const int ni  = (c4 < 17) ? 4 : 3;
    const int T   = ni * 16;

    const float* maskp = g_maskval + b * N_SEQ;

    // issue full group (K, V, 3 biases) for global tile gg into slot gg%3
    auto issue_group = [&](int gg) {
        const int j  = gg >> 4;
        const int id = (b << 7) | (c4 + 37 * j);
        const int bh = id >> 4;
        const int qb = (id & 15) * 64;
        const int kb = (gg & 15) * 64;
        const int st = gg % 3;
        const float* Kg = g_K + ((size_t)bh * N_SEQ + kb) * D_HEAD;
        const float* Vg = g_V + ((size_t)bh * N_SEQ + kb) * D_HEAD;
        float* Ka = KsB + st * 2304;
        float* Va = VsB + st * 2560;
#pragma unroll
        for (int it = 0; it < 4; it++) {
            int s = it * 128 + tid;
            int row = s >> 3;
            int cc = (s & 7) * 4;
            cp_async16(&Ka[row * 36 + cc], &Kg[row * D_HEAD + cc]);
            cp_async16(&Va[row * 40 + cc], &Vg[row * D_HEAD + cc]);
        }
        float* bbuf = Bias + st * 12288;
        const size_t base = ((size_t)bh * N_SEQ + qb) * N_SEQ + kb;
        const float* eg = edge + base;
        const float* sg = spat + base;
        const float* rg = rnk  + base;
#pragma unroll
        for (int it = 0; it < 8; it++) {
            int s = it * 128 + tid;
            int row = s >> 4;
            int ch = s & 15;
            int so = row * 64 + ((ch ^ (row & 15)) << 2);
            size_t go = (size_t)row * N_SEQ + ch * 4;
            cp_async16(&bbuf[so],        &eg[go]);
            cp_async16(&bbuf[4096 + so], &sg[go]);
            cp_async16(&bbuf[8192 + so], &rg[go]);
        }
        CP_COMMIT();
    };

    // register prefetch of item j's Q fragments (16 scalar LDGs, L2-hot)
    float qn[16];
    auto prefetch_q = [&](int j) {
        const int id = (b << 7) | (c4 + 37 * j);
        const int bh = id >> 4;
        const int qb = (id & 15) * 64;
        const float* Qg = g_Q + ((size_t)bh * N_SEQ + qb) * D_HEAD;
#pragma unroll
        for (int kk = 0; kk < 4; kk++) {
            qn[kk * 4 + 0] = Qg[(w16 + g    ) * D_HEAD + kk * 8 + t    ];
            qn[kk * 4 + 1] = Qg[(w16 + g + 8) * D_HEAD + kk * 8 + t    ];
            qn[kk * 4 + 2] = Qg[(w16 + g    ) * D_HEAD + kk * 8 + t + 4];
            qn[kk * 4 + 3] = Qg[(w16 + g + 8) * D_HEAD + kk * 8 + t + 4];
        }
    };

    // ---- Prologue: Q(item0) regs; mask group; groups for tiles 0,1,2 ----
    prefetch_q(0);
#pragma unroll
    for (int it = 0; it < 2; it++) {
        int idx = (it * 128 + tid) * 4;
        cp_async16(&Msk[idx], &maskp[idx]);
    }
    CP_COMMIT();
    issue_group(0);
    issue_group(1);
    issue_group(2);

    unsigned qa[4][4];
    float o[4][4];
    float m0 = 0.0f, m1 = 0.0f, l0 = 0.0f, l1 = 0.0f;

    for (int gt = 0; gt < T; gt++) {
        const int i = gt & 15;
        const int st = gt % 3;
        float* Ks = KsB + st * 2304;
        float* Vs = VsB + st * 2560;
        float* bbuf = Bias + st * 12288;
        const int kb = i * 64;

        // ---- item boundary: write out previous O, adopt prefetched Q ----
        if (i == 0) {
            if (gt > 0) {
                const int jp = (gt >> 4) - 1;
                const int idp = (b << 7) | (c4 + 37 * jp);
                const int bhp = idp >> 4;
                const int qbp = (idp & 15) * 64;
                const int hp  = bhp & 7;
                float inv0 = (l0 > 0.0f) ? (1.0f / l0) : 0.0f;
                float inv1 = (l1 > 0.0f) ? (1.0f / l1) : 0.0f;
                const int r0 = qbp + w16 + g;
                const int r1 = r0 + 8;
#pragma unroll
                for (int n = 0; n < 4; n++) {
                    int d = n * 8 + 2 * t;
                    float2 v0, v1;
                    v0.x = __uint_as_float(f2tf32(o[n][0] * inv0));
                    v0.y = __uint_as_float(f2tf32(o[n][1] * inv0));
                    v1.x = __uint_as_float(f2tf32(o[n][2] * inv1));
                    v1.y = __uint_as_float(f2tf32(o[n][3] * inv1));
                    *(float2*)&g_AO[((size_t)(b * N_SEQ + r0)) * D_MODEL + hp * D_HEAD + d] = v0;
                    *(float2*)&g_AO[((size_t)(b * N_SEQ + r1)) * D_MODEL + hp * D_HEAD + d] = v1;
                }
            }
#pragma unroll
            for (int kk = 0; kk < 4; kk++) {
                qa[kk][0] = __float_as_uint(qn[kk * 4 + 0]);
                qa[kk][1] = __float_as_uint(qn[kk * 4 + 1]);
                qa[kk][2] = __float_as_uint(qn[kk * 4 + 2]);
                qa[kk][3] = __float_as_uint(qn[kk * 4 + 3]);
            }
            m0 = m1 = __int_as_float(0xff800000);
            l0 = l1 = 0.0f;
#pragma unroll
            for (int n = 0; n < 4; n++)
#pragma unroll
                for (int jj = 0; jj < 4; jj++) o[n][jj] = 0.0f;
        }

        // ---- 1. wait until group(gt) complete; 2 newer groups stay in flight
        if (gt < T - 2)       { CP_WAIT2(); }
        else if (gt == T - 2) { CP_WAIT1(); }
        else                  { CP_WAIT0(); }
        __syncthreads();

        // ---- 2. S = Q K^T (Q pre-scaled by ATT_SCALE) ----
        float sc[8][4];
#pragma unroll
        for (int n8 = 0; n8 < 8; n8++) {
            sc[n8][0] = sc[n8][1] = sc[n8][2] = sc[n8][3] = 0.0f;
#pragma unroll
            for (int kk = 0; kk < 4; kk++) {
                unsigned kb2[2];
                kb2[0] = __float_as_uint(Ks[(n8 * 8 + g) * 36 + kk * 8 + t    ]);
                kb2[1] = __float_as_uint(Ks[(n8 * 8 + g) * 36 + kk * 8 + t + 4]);
                MMA_TF32(sc[n8], qa[kk], kb2);
            }
        }

        // ---- 3. combine biases (swizzled smem) + mask ----
        {
            const int r0i = w16 + g;
            const int r1i = w16 + g + 8;
            const int wi  = (2 * t) & 3;
#pragma unroll
            for (int n8 = 0; n8 < 8; n8++) {
                int ch = 2 * n8 + (t >> 1);
                int o0 = r0i * 64 + ((ch ^ (r0i & 15)) << 2) + wi;
                int o1 = r1i * 64 + ((ch ^ (r1i & 15)) << 2) + wi;
                float2 e0 = *(float2*)&bbuf[o0],        e1 = *(float2*)&bbuf[o1];
                float2 s0 = *(float2*)&bbuf[4096 + o0], s1 = *(float2*)&bbuf[4096 + o1];
                float2 r0 = *(float2*)&bbuf[8192 + o0], r1 = *(float2*)&bbuf[8192 + o1];
                float2 mk = *(float2*)&Msk[kb + n8 * 8 + 2 * t];
                sc[n8][0] += (e0.x + s0.x) + (r0.x + mk.x);
                sc[n8][1] += (e0.y + s0.y) + (r0.y + mk.y);
                sc[n8][2] += (e1.x + s1.x) + (r1.x + mk.x);
                sc[n8][3] += (e1.y + s1.y) + (r1.y + mk.y);
            }
        }

        // ---- 4. online softmax ----
        float ml0 = sc[0][0], ml1 = sc[0][2];
#pragma unroll
        for (int n8 = 0; n8 < 8; n8++) {
            ml0 = fmaxf(ml0, fmaxf(sc[n8][0], sc[n8][1]));
            ml1 = fmaxf(ml1, fmaxf(sc[n8][2], sc[n8][3]));
        }
        ml0 = fmaxf(ml0, __shfl_xor_sync(0xffffffffu, ml0, 1));
        ml0 = fmaxf(ml0, __shfl_xor_sync(0xffffffffu, ml0, 2));
        ml1 = fmaxf(ml1, __shfl_xor_sync(0xffffffffu, ml1, 1));
        ml1 = fmaxf(ml1, __shfl_xor_sync(0xffffffffu, ml1, 2));

        float mn0 = fmaxf(m0, ml0);
        float mn1 = fmaxf(m1, ml1);
        float mc0 = fmaxf(mn0, -1e30f);
        float mc1 = fmaxf(mn1, -1e30f);
        float rs0 = __expf(fmaxf(m0, -1e30f) - mc0);
        float rs1 = __expf(fmaxf(m1, -1e30f) - mc1);
        m0 = mn0; m1 = mn1;

        float sum0 = 0.0f, sum1 = 0.0f;
#pragma unroll
        for (int n8 = 0; n8 < 8; n8++) {
            float p0 = __expf(sc[n8][0] - mc0);
            float p1 = __expf(sc[n8][1] - mc0);
            float p2 = __expf(sc[n8][2] - mc1);
            float p3 = __expf(sc[n8][3] - mc1);
            sum0 += p0 + p1;
            sum1 += p2 + p3;
            float2 w0, w1;
            w0.x = __uint_as_float(f2tf32(p0)); w0.y = __uint_as_float(f2tf32(p1));
            w1.x = __uint_as_float(f2tf32(p2)); w1.y = __uint_as_float(f2tf32(p3));
            *(float2*)&Ps[(w16 + g    ) * 68 + n8 * 8 + 2 * t] = w0;
            *(float2*)&Ps[(w16 + g + 8) * 68 + n8 * 8 + 2 * t] = w1;
        }
        sum0 += __shfl_xor_sync(0xffffffffu, sum0, 1);
        sum0 += __shfl_xor_sync(0xffffffffu, sum0, 2);
        sum1 += __shfl_xor_sync(0xffffffffu, sum1, 1);
        sum1 += __shfl_xor_sync(0xffffffffu, sum1, 2);
        l0 = l0 * rs0 + sum0;
        l1 = l1 * rs1 + sum1;

#pragma unroll
        for (int n = 0; n < 4; n++) {
            o[n][0] *= rs0; o[n][1] *= rs0;
            o[n][2] *= rs1; o[n][3] *= rs1;
        }

        __syncwarp();   // this warp's Ps rows visible warp-wide

        // ---- 5. O += P V ----
#pragma unroll
        for (int kk = 0; kk < 8; kk++) {
            unsigned pa[4];
            pa[0] = __float_as_uint(Ps[(w16 + g    ) * 68 + kk * 8 + t    ]);
            pa[1] = __float_as_uint(Ps[(w16 + g + 8) * 68 + kk * 8 + t    ]);
            pa[2] = __float_as_uint(Ps[(w16 + g    ) * 68 + kk * 8 + t + 4]);
            pa[3] = __float_as_uint(Ps[(w16 + g + 8) * 68 + kk * 8 + t + 4]);
#pragma unroll
            for (int n = 0; n < 4; n++) {
                unsigned vb[2];
                vb[0] = __float_as_uint(Vs[(kk * 8 + t    ) * 40 + n * 8 + g]);
                vb[1] = __float_as_uint(Vs[(kk * 8 + t + 4) * 40 + n * 8 + g]);
                MMA_TF32(o[n], pa, vb);
            }
        }

        // ---- 6. slot fully consumed -> refill with group(gt+3); Q prefetch
        __syncthreads();
        if (gt + 3 < T) issue_group(gt + 3);
        if (i == 13 && (gt >> 4) + 1 < ni) prefetch_q((gt >> 4) + 1);
    }

    // ---- final item writeback ----
    {
        const int jp = ni - 1;
        const int idp = (b << 7) | (c4 + 37 * jp);
        const int bhp = idp >> 4;
        const int qbp = (idp & 15) * 64;
        const int hp  = bhp & 7;
        float inv0 = (l0 > 0.0f) ? (1.0f / l0) : 0.0f;
        float inv1 = (l1 > 0.0f) ? (1.0f / l1) : 0.0f;
        const int r0 = qbp + w16 + g;
        const int r1 = r0 + 8;
#pragma unroll
        for (int n = 0; n < 4; n++) {
            int d = n * 8 + 2 * t;
            float2 v0, v1;
            v0.x = __uint_as_float(f2tf32(o[n][0] * inv0));
            v0.y = __uint_as_float(f2tf32(o[n][1] * inv0));
            v1.x = __uint_as_float(f2tf32(o[n][2] * inv1));
            v1.y = __uint_as_float(f2tf32(o[n][3] * inv1));
            *(float2*)&g_AO[((size_t)(b * N_SEQ + r0)) * D_MODEL + hp * D_HEAD + d] = v0;
            *(float2*)&g_AO[((size_t)(b * N_SEQ + r1)) * D_MODEL + hp * D_HEAD + d] = v1;
        }
    }
}

// ---------------------------------------------------------------------------
extern "C" void kernel_launch(void* const* d_in, const int* in_sizes, int n_in,
                              void* d_out, int out_size)
{
    const float* x    = (const float*)d_in[0];
    const float* edge = (const float*)d_in[1];
    const float* spat = (const float*)d_in[2];
    const float* rnk  = (const float*)d_in[3];
    const void*  mask = d_in[4];
    const float* Wq = (const float*)d_in[5];
    const float* bq = (const float*)d_in[6];
    const float* Wk = (const float*)d_in[7];
    const float* bk = (const float*)d_in[8];
    const float* Wv = (const float*)d_in[9];
    const float* bv = (const float*)d_in[10];
    const float* Wo = (const float*)d_in[11];
    const float* bo = (const float*)d_in[12];

    cudaFuncSetAttribute(attn_tc_kernel,
                         cudaFuncAttributeMaxDynamicSharedMemorySize,
                         ATTN_SMEM_BYTES);

    prep_mask_kernel<<<1, 256>>>(mask);

    gemm_qkv_tc<<<dim3(64, 4, 3), 128>>>(x, Wq, Wk, Wv, bq, bk, bv);

    attn_tc_kernel<<<148, 128, ATTN_SMEM_BYTES>>>(edge, spat, rnk);

    gemm_o_tc<<<dim3(64, 4), 128>>>(Wo, bo, (float*)d_out);
}

// round 9
// speedup vs baseline: 1.1220x; 1.1220x over previous
#include <cuda_runtime.h>
#include <math.h>

#define BATCH   4
#define N_SEQ   1024
#define D_MODEL 256
#define N_HEADS 8
#define D_HEAD  32
#define ATT_SCALE 0.17677669529663687f   // 1/sqrt(32)

// Scratch (device globals: no allocation allowed in kernel_launch)
__device__ float g_Q[BATCH * N_HEADS * N_SEQ * D_HEAD];   // [b,h,n,dk]  tf32, pre-scaled
__device__ float g_K[BATCH * N_HEADS * N_SEQ * D_HEAD];   // tf32-rounded
__device__ float g_V[BATCH * N_HEADS * N_SEQ * D_HEAD];   // tf32-rounded
__device__ float g_AO[BATCH * N_SEQ * D_MODEL];           // attention out, tf32-rounded
__device__ float g_maskval[BATCH * N_SEQ];                // 0 or -inf per key

__device__ __forceinline__ unsigned f2tf32(float f) {
    unsigned u;
    asm("cvt.rna.tf32.f32 %0, %1;" : "=r"(u) : "f"(f));
    return u;
}

#define MMA_TF32(d, a, b)                                                     \
    asm volatile(                                                             \
        "mma.sync.aligned.m16n8k8.row.col.f32.tf32.tf32.f32 "                 \
        "{%0,%1,%2,%3}, {%4,%5,%6,%7}, {%8,%9}, {%0,%1,%2,%3};\n"             \
        : "+f"((d)[0]), "+f"((d)[1]), "+f"((d)[2]), "+f"((d)[3])              \
        : "r"((a)[0]), "r"((a)[1]), "r"((a)[2]), "r"((a)[3]),                 \
          "r"((b)[0]), "r"((b)[1]))

__device__ __forceinline__ void cp_async16(void* s, const void* g) {
    unsigned sa = (unsigned)__cvta_generic_to_shared(s);
    asm volatile("cp.async.cg.shared.global [%0], [%1], 16;" :: "r"(sa), "l"(g));
}
#define CP_COMMIT() asm volatile("cp.async.commit_group;")
#define CP_WAIT0()  asm volatile("cp.async.wait_group 0;")
#define CP_WAIT1()  asm volatile("cp.async.wait_group 1;")
#define CP_WAIT2()  asm volatile("cp.async.wait_group 2;")

// ---------------------------------------------------------------------------
// Fused QKV projection (tile 128x64, 256 threads, 2-stage cp.async) with the
// mask prep folded into block (0,0,0). grid=(32,4,3).
// Q additionally scaled by ATT_SCALE; outputs tf32-rounded to [b,h,n,dk].
// ---------------------------------------------------------------------------
#define GEMM_SMEM_BYTES (13824 * 4)   // As 2*128*36 + Ws 2*64*36 floats

__global__ __launch_bounds__(256) void gemm_qkv_tc(
    const float* __restrict__ x,
    const float* __restrict__ Wq, const float* __restrict__ Wk, const float* __restrict__ Wv,
    const float* __restrict__ bq, const float* __restrict__ bk, const float* __restrict__ bv,
    const void* __restrict__ mraw)
{
    extern __shared__ float sm[];
    float* As = sm;            // [2][128][36]
    float* Ws = sm + 9216;     // [2][64][36]

    // ---- mask prep (one block only; attn reads it in the NEXT launch) ----
    if (blockIdx.x == 0 && blockIdx.y == 0 && blockIdx.z == 0) {
        const int tid = threadIdx.x;
        const unsigned* mi = (const unsigned*)mraw;
        int ok_int = 1, ok_float = 1;
        for (int i = tid; i < 1024; i += 256) {
            unsigned v = mi[i];
            if (v > 1u) ok_int = 0;
            if (v != 0u && v != 0x3F800000u) ok_float = 0;
        }
        int all_int   = __syncthreads_and(ok_int);
        int all_float = __syncthreads_and(ok_float);
        const int mode = all_int ? 0 : (all_float ? 1 : 2);
        const float NEG_INF = __int_as_float(0xff800000);
        for (int i = tid; i < BATCH * N_SEQ; i += 256) {
            int masked;
            if (mode == 0)      masked = ((const int*)mraw)[i] != 0;
            else if (mode == 1) masked = ((const unsigned*)mraw)[i] != 0u;
            else                masked = ((const unsigned char*)mraw)[i] != 0;
            g_maskval[i] = masked ? NEG_INF : 0.0f;
        }
    }

    const int z = blockIdx.z;
    const float* W    = (z == 0) ? Wq : (z == 1) ? Wk : Wv;
    const float* bias = (z == 0) ? bq : (z == 1) ? bk : bv;
    float* out        = (z == 0) ? g_Q : (z == 1) ? g_K : g_V;

    const int tid  = threadIdx.x;
    const int lane = tid & 31;
    const int w    = tid >> 5;        // 0..7
    const int g    = lane >> 2;
    const int t    = lane & 3;
    const int w16  = w * 16;
    const int rbase = blockIdx.x * 128;
    const int cbase = blockIdx.y * 64;

    float sc[8][4];
#pragma unroll
    for (int n = 0; n < 8; n++)
#pragma unroll
        for (int j = 0; j < 4; j++) sc[n][j] = 0.0f;

    auto prefetch = [&](int c) {
        const int k0 = c * 32, st = c & 1;
        float* Ap = As + st * 4608;
        float* Wp = Ws + st * 2304;
#pragma unroll
        for (int it = 0; it < 4; it++) {
            int s = it * 256 + tid;
            int row = s >> 3;
            int c4 = (s & 7) * 4;
            cp_async16(&Ap[row * 36 + c4], &x[(size_t)(rbase + row) * D_MODEL + k0 + c4]);
        }
#pragma unroll
        for (int it = 0; it < 2; it++) {
            int s = it * 256 + tid;
            int row = s >> 3;
            int c4 = (s & 7) * 4;
            cp_async16(&Wp[row * 36 + c4], &W[(size_t)(cbase + row) * D_MODEL + k0 + c4]);
        }
        CP_COMMIT();
    };

    prefetch(0);
    for (int c = 0; c < 8; c++) {
        const int st = c & 1;
        const float* Ap = As + st * 4608;
        const float* Wp = Ws + st * 2304;
        if (c < 7) { prefetch(c + 1); CP_WAIT1(); }
        else       { CP_WAIT0(); }
        __syncthreads();

        unsigned qa[4][4];
#pragma unroll
        for (int kk = 0; kk < 4; kk++) {
            qa[kk][0] = f2tf32(Ap[(w16 + g    ) * 36 + kk * 8 + t    ]);
            qa[kk][1] = f2tf32(Ap[(w16 + g + 8) * 36 + kk * 8 + t    ]);
            qa[kk][2] = f2tf32(Ap[(w16 + g    ) * 36 + kk * 8 + t + 4]);
            qa[kk][3] = f2tf32(Ap[(w16 + g + 8) * 36 + kk * 8 + t + 4]);
        }
#pragma unroll
        for (int n8 = 0; n8 < 8; n8++) {
#pragma unroll
            for (int kk = 0; kk < 4; kk++) {
                unsigned bb[2];
                bb[0] = f2tf32(Wp[(n8 * 8 + g) * 36 + kk * 8 + t    ]);
                bb[1] = f2tf32(Wp[(n8 * 8 + g) * 36 + kk * 8 + t + 4]);
                MMA_TF32(sc[n8], qa[kk], bb);
            }
        }
        __syncthreads();
    }

    const float scale = (z == 0) ? ATT_SCALE : 1.0f;
#pragma unroll
    for (int n8 = 0; n8 < 8; n8++) {
        int c0 = cbase + n8 * 8 + 2 * t;
        float b0v = bias[c0], b1v = bias[c0 + 1];
        int r0 = rbase + w16 + g;
        int r1 = r0 + 8;
        float2 v0, v1;
        v0.x = __uint_as_float(f2tf32((sc[n8][0] + b0v) * scale));
        v0.y = __uint_as_float(f2tf32((sc[n8][1] + b1v) * scale));
        v1.x = __uint_as_float(f2tf32((sc[n8][2] + b0v) * scale));
        v1.y = __uint_as_float(f2tf32((sc[n8][3] + b1v) * scale));
        int h = c0 >> 5, dk = c0 & 31;
        int b0i = r0 >> 10, n0 = r0 & 1023;
        int b1i = r1 >> 10, n1 = r1 & 1023;
        *(float2*)&out[(size_t)(((b0i << 3) + h) * N_SEQ + n0) * D_HEAD + dk] = v0;
        *(float2*)&out[(size_t)(((b1i << 3) + h) * N_SEQ + n1) * D_HEAD + dk] = v1;
    }
}

// ---------------------------------------------------------------------------
// Output projection (tile 128x64, 256 threads, 2-stage cp.async). grid=(32,4).
// ---------------------------------------------------------------------------
__global__ __launch_bounds__(256) void gemm_o_tc(
    const float* __restrict__ W, const float* __restrict__ bias,
    float* __restrict__ out)
{
    extern __shared__ float sm[];
    float* As = sm;            // [2][128][36]
    float* Ws = sm + 9216;     // [2][64][36]

    const int tid  = threadIdx.x;
    const int lane = tid & 31;
    const int w    = tid >> 5;
    const int g    = lane >> 2;
    const int t    = lane & 3;
    const int w16  = w * 16;
    const int rbase = blockIdx.x * 128;
    const int cbase = blockIdx.y * 64;

    float sc[8][4];
#pragma unroll
    for (int n = 0; n < 8; n++)
#pragma unroll
        for (int j = 0; j < 4; j++) sc[n][j] = 0.0f;

    auto prefetch = [&](int c) {
        const int k0 = c * 32, st = c & 1;
        float* Ap = As + st * 4608;
        float* Wp = Ws + st * 2304;
#pragma unroll
        for (int it = 0; it < 4; it++) {
            int s = it * 256 + tid;
            int row = s >> 3;
            int c4 = (s & 7) * 4;
            cp_async16(&Ap[row * 36 + c4], &g_AO[(size_t)(rbase + row) * D_MODEL + k0 + c4]);
        }
#pragma unroll
        for (int it = 0; it < 2; it++) {
            int s = it * 256 + tid;
            int row = s >> 3;
            int c4 = (s & 7) * 4;
            cp_async16(&Wp[row * 36 + c4], &W[(size_t)(cbase + row) * D_MODEL + k0 + c4]);
        }
        CP_COMMIT();
    };

    prefetch(0);
    for (int c = 0; c < 8; c++) {
        const int st = c & 1;
        const float* Ap = As + st * 4608;
        const float* Wp = Ws + st * 2304;
        if (c < 7) { prefetch(c + 1); CP_WAIT1(); }
        else       { CP_WAIT0(); }
        __syncthreads();

        unsigned qa[4][4];
#pragma unroll
        for (int kk = 0; kk < 4; kk++) {
            qa[kk][0] = __float_as_uint(Ap[(w16 + g    ) * 36 + kk * 8 + t    ]);
            qa[kk][1] = __float_as_uint(Ap[(w16 + g + 8) * 36 + kk * 8 + t    ]);
            qa[kk][2] = __float_as_uint(Ap[(w16 + g    ) * 36 + kk * 8 + t + 4]);
            qa[kk][3] = __float_as_uint(Ap[(w16 + g + 8) * 36 + kk * 8 + t + 4]);
        }
#pragma unroll
        for (int n8 = 0; n8 < 8; n8++) {
#pragma unroll
            for (int kk = 0; kk < 4; kk++) {
                unsigned bb[2];
                bb[0] = f2tf32(Wp[(n8 * 8 + g) * 36 + kk * 8 + t    ]);
                bb[1] = f2tf32(Wp[(n8 * 8 + g) * 36 + kk * 8 + t + 4]);
                MMA_TF32(sc[n8], qa[kk], bb);
            }
        }
        __syncthreads();
    }

#pragma unroll
    for (int n8 = 0; n8 < 8; n8++) {
        int c0 = cbase + n8 * 8 + 2 * t;
        float b0v = bias[c0], b1v = bias[c0 + 1];
        int r0 = rbase + w16 + g;
        int r1 = r0 + 8;
        float2 v0, v1;
        v0.x = sc[n8][0] + b0v;  v0.y = sc[n8][1] + b1v;
        v1.x = sc[n8][2] + b0v;  v1.y = sc[n8][3] + b1v;
        *(float2*)&out[(size_t)r0 * D_MODEL + c0] = v0;
        *(float2*)&out[(size_t)r1 * D_MODEL + c0] = v1;
    }
}

// ---------------------------------------------------------------------------
// Tensor-core flash attention — EXACT round-5 config (best: 147.5us).
// grid=(16,32), block=128 (4 warps), 108.5 KB dynamic smem -> 2 CTAs/SM.
// Dynamic smem layout (floats):
//   KsB[2][64][36]  @ 0      (4608)
//   VsB[2][64][40]  @ 4608   (5120)
//   Ps  [64][68]    @ 9728   (4352)   (also Q staging in prologue)
//   BE/BS/BR [64][68] each @ 14080/18432.../...  (bias stage, 1 tile ahead)
// total 27136 floats = 108544 B
// ---------------------------------------------------------------------------
#define ATTN_SMEM_BYTES (27136 * 4)

__global__ __launch_bounds__(128) void attn_tc_kernel(
    const float* __restrict__ edge,
    const float* __restrict__ spat,
    const float* __restrict__ rnk)
{
    extern __shared__ float dsm[];
    float* KsB = dsm;                 // 2 * 64*36
    float* VsB = dsm + 4608;          // 2 * 64*40
    float* Ps  = dsm + 9728;          // 64*68
    float* BE  = dsm + 14080;         // 64*68
    float* BS  = BE + 4352;
    float* BR  = BS + 4352;

    const int tid  = threadIdx.x;
    const int lane = tid & 31;
    const int w    = tid >> 5;
    const int g    = lane >> 2;
    const int t    = lane & 3;
    const int qb   = blockIdx.x * 64;
    const int bh   = blockIdx.y;
    const int b    = bh >> 3;
    const int h    = bh & 7;
    const int w16  = w * 16;

    const float* Kg0 = g_K + (size_t)bh * N_SEQ * D_HEAD;
    const float* Vg0 = g_V + (size_t)bh * N_SEQ * D_HEAD;
    const float* maskp = g_maskval + b * N_SEQ;
    const float* eg0 = edge + ((size_t)bh * N_SEQ + qb) * N_SEQ;
    const float* sg0 = spat + ((size_t)bh * N_SEQ + qb) * N_SEQ;
    const float* rg0 = rnk  + ((size_t)bh * N_SEQ + qb) * N_SEQ;

    // issue K/V(0) + bias(0) as one group
    {
        const float* Kg = Kg0;
        const float* Vg = Vg0;
#pragma unroll
        for (int it = 0; it < 4; it++) {
            int s = it * 128 + tid;
            int row = s >> 3;
            int c4 = (s & 7) * 4;
            cp_async16(&KsB[row * 36 + c4], &Kg[row * D_HEAD + c4]);
            cp_async16(&VsB[row * 40 + c4], &Vg[row * D_HEAD + c4]);
        }
#pragma unroll
        for (int it = 0; it < 8; it++) {
            int s = it * 128 + tid;
            int row = s >> 4;
            int c4 = (s & 15) * 4;
            size_t go = (size_t)row * N_SEQ + c4;
            int so = row * 68 + c4;
            cp_async16(&BE[so], &eg0[go]);
            cp_async16(&BS[so], &sg0[go]);
            cp_async16(&BR[so], &rg0[go]);
        }
        CP_COMMIT();
    }

    // stage Q through Ps, extract fragments
    const float* Qg = g_Q + ((size_t)bh * N_SEQ + qb) * D_HEAD;
#pragma unroll
    for (int it = 0; it < 4; it++) {
        int s = it * 128 + tid;
        int row = s >> 3;
        int c4 = (s & 7) * 4;
        cp_async16(&Ps[row * 68 + c4], &Qg[row * D_HEAD + c4]);
    }
    CP_COMMIT();
    CP_WAIT0();
    __syncthreads();

    unsigned qa[4][4];
#pragma unroll
    for (int kk = 0; kk < 4; kk++) {
        qa[kk][0] = __float_as_uint(Ps[(w16 + g    ) * 68 + kk * 8 + t    ]);
        qa[kk][1] = __float_as_uint(Ps[(w16 + g + 8) * 68 + kk * 8 + t    ]);
        qa[kk][2] = __float_as_uint(Ps[(w16 + g    ) * 68 + kk * 8 + t + 4]);
        qa[kk][3] = __float_as_uint(Ps[(w16 + g + 8) * 68 + kk * 8 + t + 4]);
    }

    // mask regs for tile 0
    float2 mkc[8];
#pragma unroll
    for (int n8 = 0; n8 < 8; n8++)
        mkc[n8] = *(const float2*)&maskp[n8 * 8 + 2 * t];

    float o[4][4];
#pragma unroll
    for (int n = 0; n < 4; n++)
#pragma unroll
        for (int j = 0; j < 4; j++) o[n][j] = 0.0f;

    float m0 = __int_as_float(0xff800000), m1 = m0;
    float l0 = 0.0f, l1 = 0.0f;

    for (int i = 0; i < 16; i++) {
        const int kb = i * 64;
        const int cur = i & 1;
        float* Ks = KsB + cur * 2304;
        float* Vs = VsB + cur * 2560;

        // 1. group(i) arrived; also: every warp finished tile i-1 entirely
        CP_WAIT0();
        __syncthreads();

        // 2. S = Q K^T (Q pre-scaled by ATT_SCALE)
        float sc[8][4];
#pragma unroll
        for (int n8 = 0; n8 < 8; n8++) {
            sc[n8][0] = sc[n8][1] = sc[n8][2] = sc[n8][3] = 0.0f;
#pragma unroll
            for (int kk = 0; kk < 4; kk++) {
                unsigned bb[2];
                bb[0] = __float_as_uint(Ks[(n8 * 8 + g) * 36 + kk * 8 + t    ]);
                bb[1] = __float_as_uint(Ks[(n8 * 8 + g) * 36 + kk * 8 + t + 4]);
                MMA_TF32(sc[n8], qa[kk], bb);
            }
        }

        // 3. combine biases (from smem stage) + mask (regs)
#pragma unroll
        for (int n8 = 0; n8 < 8; n8++) {
            int c0 = n8 * 8 + 2 * t;
            int ro0 = (w16 + g    ) * 68 + c0;
            int ro1 = (w16 + g + 8) * 68 + c0;
            float2 e0 = *(float2*)&BE[ro0], e1 = *(float2*)&BE[ro1];
            float2 s0 = *(float2*)&BS[ro0], s1 = *(float2*)&BS[ro1];
            float2 r0 = *(float2*)&BR[ro0], r1 = *(float2*)&BR[ro1];
            float2 mk = mkc[n8];
            sc[n8][0] += (e0.x + s0.x) + (r0.x + mk.x);
            sc[n8][1] += (e0.y + s0.y) + (r0.y + mk.y);
            sc[n8][2] += (e1.x + s1.x) + (r1.x + mk.x);
            sc[n8][3] += (e1.y + s1.y) + (r1.y + mk.y);
        }

        // online softmax
        float ml0 = sc[0][0], ml1 = sc[0][2];
#pragma unroll
        for (int n8 = 0; n8 < 8; n8++) {
            ml0 = fmaxf(ml0, fmaxf(sc[n8][0], sc[n8][1]));
            ml1 = fmaxf(ml1, fmaxf(sc[n8][2], sc[n8][3]));
        }
        ml0 = fmaxf(ml0, __shfl_xor_sync(0xffffffffu, ml0, 1));
        ml0 = fmaxf(ml0, __shfl_xor_sync(0xffffffffu, ml0, 2));
        ml1 = fmaxf(ml1, __shfl_xor_sync(0xffffffffu, ml1, 1));
        ml1 = fmaxf(ml1, __shfl_xor_sync(0xffffffffu, ml1, 2));

        float mn0 = fmaxf(m0, ml0);
        float mn1 = fmaxf(m1, ml1);
        float mc0 = fmaxf(mn0, -1e30f);
        float mc1 = fmaxf(mn1, -1e30f);
        float rs0 = __expf(fmaxf(m0, -1e30f) - mc0);
        float rs1 = __expf(fmaxf(m1, -1e30f) - mc1);
        m0 = mn0; m1 = mn1;

        float sum0 = 0.0f, sum1 = 0.0f;
#pragma unroll
        for (int n8 = 0; n8 < 8; n8++) {
            float p0 = __expf(sc[n8][0] - mc0);
            float p1 = __expf(sc[n8][1] - mc0);
            float p2 = __expf(sc[n8][2] - mc1);
            float p3 = __expf(sc[n8][3] - mc1);
            sum0 += p0 + p1;
            sum1 += p2 + p3;
            float2 w0, w1;
            w0.x = __uint_as_float(f2tf32(p0)); w0.y = __uint_as_float(f2tf32(p1));
            w1.x = __uint_as_float(f2tf32(p2)); w1.y = __uint_as_float(f2tf32(p3));
            *(float2*)&Ps[(w16 + g    ) * 68 + n8 * 8 + 2 * t] = w0;
            *(float2*)&Ps[(w16 + g + 8) * 68 + n8 * 8 + 2 * t] = w1;
        }
        sum0 += __shfl_xor_sync(0xffffffffu, sum0, 1);
        sum0 += __shfl_xor_sync(0xffffffffu, sum0, 2);
        sum1 += __shfl_xor_sync(0xffffffffu, sum1, 1);
        sum1 += __shfl_xor_sync(0xffffffffu, sum1, 2);
        l0 = l0 * rs0 + sum0;
        l1 = l1 * rs1 + sum1;

#pragma unroll
        for (int n = 0; n < 4; n++) {
            o[n][0] *= rs0; o[n][1] *= rs0;
            o[n][2] *= rs1; o[n][3] *= rs1;
        }

        // 4. all warps done with bias stage (and prior alt K/V)
        __syncthreads();

        // 5. issue group(i+1): K/V into alt stage, biases into stage, mask regs
        if (i < 15) {
            const int kbn = kb + 64;
            const int alt = 1 - cur;
            const float* Kg = Kg0 + (size_t)kbn * D_HEAD;
            const float* Vg = Vg0 + (size_t)kbn * D_HEAD;
            float* Ka = KsB + alt * 2304;
            float* Va = VsB + alt * 2560;
#pragma unroll
            for (int it = 0; it < 4; it++) {
                int s = it * 128 + tid;
                int row = s >> 3;
                int c4 = (s & 7) * 4;
                cp_async16(&Ka[row * 36 + c4], &Kg[row * D_HEAD + c4]);
                cp_async16(&Va[row * 40 + c4], &Vg[row * D_HEAD + c4]);
            }
            const float* eg = eg0 + kbn;
            const float* sg = sg0 + kbn;
            const float* rg = rg0 + kbn;
#pragma unroll
            for (int it = 0; it < 8; it++) {
                int s = it * 128 + tid;
                int row = s >> 4;
                int c4 = (s & 15) * 4;
                size_t go = (size_t)row * N_SEQ + c4;
                int so = row * 68 + c4;
                cp_async16(&BE[so], &eg[go]);
                cp_async16(&BS[so], &sg[go]);
                cp_async16(&BR[so], &rg[go]);
            }
            CP_COMMIT();
#pragma unroll
            for (int n8 = 0; n8 < 8; n8++)
                mkc[n8] = *(const float2*)&maskp[kbn + n8 * 8 + 2 * t];
        }

        __syncwarp();   // this warp's Ps rows visible warp-wide

        // 6. O += P V
#pragma unroll
        for (int kk = 0; kk < 8; kk++) {
            unsigned pa[4];
            pa[0] = __float_as_uint(Ps[(w16 + g    ) * 68 + kk * 8 + t    ]);
            pa[1] = __float_as_uint(Ps[(w16 + g + 8) * 68 + kk * 8 + t    ]);
            pa[2] = __float_as_uint(Ps[(w16 + g    ) * 68 + kk * 8 + t + 4]);
            pa[3] = __float_as_uint(Ps[(w16 + g + 8) * 68 + kk * 8 + t + 4]);
#pragma unroll
            for (int n = 0; n < 4; n++) {
                unsigned bb[2];
                bb[0] = __float_as_uint(Vs[(kk * 8 + t    ) * 40 + n * 8 + g]);
                bb[1] = __float_as_uint(Vs[(kk * 8 + t + 4) * 40 + n * 8 + g]);
                MMA_TF32(o[n], pa, bb);
            }
        }
    }

    // normalize + scatter (tf32-rounded for the O-projection mma)
    float inv0 = (l0 > 0.0f) ? (1.0f / l0) : 0.0f;
    float inv1 = (l1 > 0.0f) ? (1.0f / l1) : 0.0f;
    const int r0 = qb + w16 + g;
    const int r1 = r0 + 8;
#pragma unroll
    for (int n = 0; n < 4; n++) {
        int d = n * 8 + 2 * t;
        float2 v0, v1;
        v0.x = __uint_as_float(f2tf32(o[n][0] * inv0));
        v0.y = __uint_as_float(f2tf32(o[n][1] * inv0));
        v1.x = __uint_as_float(f2tf32(o[n][2] * inv1));
        v1.y = __uint_as_float(f2tf32(o[n][3] * inv1));
        *(float2*)&g_AO[((size_t)(b * N_SEQ + r0)) * D_MODEL + h * D_HEAD + d] = v0;
        *(float2*)&g_AO[((size_t)(b * N_SEQ + r1)) * D_MODEL + h * D_HEAD + d] = v1;
    }
}

// ---------------------------------------------------------------------------
extern "C" void kernel_launch(void* const* d_in, const int* in_sizes, int n_in,
                              void* d_out, int out_size)
{
    const float* x    = (const float*)d_in[0];
    const float* edge = (const float*)d_in[1];
    const float* spat = (const float*)d_in[2];
    const float* rnk  = (const float*)d_in[3];
    const void*  mask = d_in[4];
    const float* Wq = (const float*)d_in[5];
    const float* bq = (const float*)d_in[6];
    const float* Wk = (const float*)d_in[7];
    const float* bk = (const float*)d_in[8];
    const float* Wv = (const float*)d_in[9];
    const float* bv = (const float*)d_in[10];
    const float* Wo = (const float*)d_in[11];
    const float* bo = (const float*)d_in[12];

    cudaFuncSetAttribute(attn_tc_kernel,
                         cudaFuncAttributeMaxDynamicSharedMemorySize,
                         ATTN_SMEM_BYTES);
    cudaFuncSetAttribute(gemm_qkv_tc,
                         cudaFuncAttributeMaxDynamicSharedMemorySize,
                         GEMM_SMEM_BYTES);
    cudaFuncSetAttribute(gemm_o_tc,
                         cudaFuncAttributeMaxDynamicSharedMemorySize,
                         GEMM_SMEM_BYTES);

    gemm_qkv_tc<<<dim3(32, 4, 3), 256, GEMM_SMEM_BYTES>>>(
        x, Wq, Wk, Wv, bq, bk, bv, mask);

    attn_tc_kernel<<<dim3(16, 32), 128, ATTN_SMEM_BYTES>>>(edge, spat, rnk);

    gemm_o_tc<<<dim3(32, 4), 256, GEMM_SMEM_BYTES>>>(Wo, bo, (float*)d_out);
}